// round 2
// baseline (speedup 1.0000x reference)
#include <cuda_runtime.h>
#include <math.h>

#define B_   2
#define S_   2048
#define HID_ 2048
#define NH_  16
#define HD_  128
#define ROT_ 64
#define M_   (B_*S_)          // 4096 rows in QKV GEMM

// ---------------- scratch (no allocations allowed) ----------------
__device__ float g_Q[(size_t)B_*NH_*S_*HD_];
__device__ float g_K[(size_t)B_*NH_*S_*HD_];
__device__ float g_V[(size_t)B_*NH_*S_*HD_];

// ================= fused QKV projection + bias + RoPE =================
#define GBM 64
#define GBN 64
#define GBK 16

__global__ __launch_bounds__(256)
void qkv_kernel(const float* __restrict__ H,
                const float* __restrict__ Wq, const float* __restrict__ bq,
                const float* __restrict__ Wk, const float* __restrict__ bk,
                const float* __restrict__ Wv, const float* __restrict__ bv)
{
    __shared__ __align__(16) float As[GBK][GBM];
    __shared__ __align__(16) float Bs[GBK][GBN];

    const int z = blockIdx.z;
    const float* W    = (z==0) ? Wq : (z==1) ? Wk : Wv;
    const float* bias = (z==0) ? bq : (z==1) ? bk : bv;
    float*       Obuf = (z==0) ? g_Q : (z==1) ? g_K : g_V;

    const int tid = threadIdx.x;
    const int tx = tid & 15, ty = tid >> 4;
    const int m0 = blockIdx.y * GBM, n0 = blockIdx.x * GBN;
    const int lr = tid >> 2;          // 0..63 row within tile
    const int lk = (tid & 3) * 4;     // 0,4,8,12 k-offset

    float acc[4][4] = {};
    const float* Arow = H + (size_t)(m0+lr)*HID_ + lk;
    const float* Brow = W + (size_t)(n0+lr)*HID_ + lk;

    for (int k0 = 0; k0 < HID_; k0 += GBK) {
        float4 a = *(const float4*)(Arow + k0);
        float4 b = *(const float4*)(Brow + k0);
        As[lk+0][lr]=a.x; As[lk+1][lr]=a.y; As[lk+2][lr]=a.z; As[lk+3][lr]=a.w;
        Bs[lk+0][lr]=b.x; Bs[lk+1][lr]=b.y; Bs[lk+2][lr]=b.z; Bs[lk+3][lr]=b.w;
        __syncthreads();
        #pragma unroll
        for (int kk = 0; kk < GBK; kk++) {
            float4 a4 = *(const float4*)&As[kk][ty*4];
            float4 b4 = *(const float4*)&Bs[kk][tx*4];
            float av[4] = {a4.x,a4.y,a4.z,a4.w};
            float bw[4] = {b4.x,b4.y,b4.z,b4.w};
            #pragma unroll
            for (int i=0;i<4;i++)
                #pragma unroll
                for (int j=0;j<4;j++)
                    acc[i][j] = fmaf(av[i], bw[j], acc[i][j]);
        }
        __syncthreads();
    }

    // epilogue: bias + RoPE on first ROT dims of each head (Q,K only)
    #pragma unroll
    for (int i=0;i<4;i++) {
        const int m  = m0 + ty*4 + i;
        const int bb = m / S_;
        const int s  = m % S_;
        #pragma unroll
        for (int j=0;j<4;j+=2) {
            const int n = n0 + tx*4 + j;     // even
            const int h = n / HD_;
            const int d = n % HD_;           // even
            float x = acc[i][j]   + bias[n];
            float y = acc[i][j+1] + bias[n+1];
            if (z < 2 && d < ROT_) {
                float inv = powf(10000.0f, -(float)d / (float)ROT_);
                float ang = (float)s * inv;
                float sn, cs; sincosf(ang, &sn, &cs);
                float nx = x*cs - y*sn;
                float ny = y*cs + x*sn;
                x = nx; y = ny;
            }
            size_t o = (((size_t)bb*NH_ + h)*S_ + s)*HD_ + d;
            Obuf[o]   = x;
            Obuf[o+1] = y;
        }
    }
}

// ================= causal flash attention (fp32) =================
#define QSTR 129                     // padded row stride for Q/K tiles

// shared layout (floats): Qs 64*129 | Ks 64*129 | Vs 64*128 | SS 64*65 | m,l,alpha 3*64
#define SMEM_FLOATS (64*QSTR + 64*QSTR + 64*128 + 64*65 + 3*64)
#define SMEM_BYTES  (SMEM_FLOATS * 4)

__global__ __launch_bounds__(256)
void attn_kernel(const float* __restrict__ amask, float* __restrict__ out)
{
    extern __shared__ __align__(16) float sm[];
    float* Qs   = sm;
    float* Ks   = Qs + 64*QSTR;
    float* Vs   = Ks + 64*QSTR;
    float* SS   = Vs + 64*128;
    float* mrow = SS + 64*65;
    float* lrow = mrow + 64;
    float* arow = lrow + 64;

    const int qt = blockIdx.x, h = blockIdx.y, b = blockIdx.z;
    const float* Q = g_Q + ((size_t)b*NH_ + h)*S_*HD_;
    const float* K = g_K + ((size_t)b*NH_ + h)*S_*HD_;
    const float* V = g_V + ((size_t)b*NH_ + h)*S_*HD_;

    const int tid = threadIdx.x;
    const int tx = tid & 15, ty = tid >> 4;

    // load Q tile (64 x 128) into padded smem
    #pragma unroll
    for (int it = 0; it < 8; it++) {
        int idx = tid + it*256;          // 0..2047 float4 slots
        int r = idx >> 5;
        int c = (idx & 31) * 4;
        float4 v = *(const float4*)&Q[(size_t)(qt*64 + r)*HD_ + c];
        Qs[r*QSTR + c+0]=v.x; Qs[r*QSTR + c+1]=v.y;
        Qs[r*QSTR + c+2]=v.z; Qs[r*QSTR + c+3]=v.w;
    }
    if (tid < 64) { mrow[tid] = -INFINITY; lrow[tid] = 0.f; }

    float o[4][8];
    #pragma unroll
    for (int i=0;i<4;i++)
        #pragma unroll
        for (int c=0;c<8;c++) o[i][c]=0.f;

    __syncthreads();

    const float scale = 0.08838834764831845f;   // 1/sqrt(128)

    for (int kt = 0; kt <= qt; kt++) {
        // load K,V tiles
        #pragma unroll
        for (int it = 0; it < 8; it++) {
            int idx = tid + it*256;
            int r = idx >> 5;
            int c = (idx & 31) * 4;
            float4 kv = *(const float4*)&K[(size_t)(kt*64 + r)*HD_ + c];
            Ks[r*QSTR + c+0]=kv.x; Ks[r*QSTR + c+1]=kv.y;
            Ks[r*QSTR + c+2]=kv.z; Ks[r*QSTR + c+3]=kv.w;
            float4 vv = *(const float4*)&V[(size_t)(kt*64 + r)*HD_ + c];
            *(float4*)&Vs[r*128 + c] = vv;
        }
        __syncthreads();

        // S = Q K^T  (64x64, 4x4 per thread)
        float sacc[4][4] = {};
        #pragma unroll 4
        for (int d = 0; d < HD_; d++) {
            float a[4], kk4[4];
            #pragma unroll
            for (int i=0;i<4;i++) a[i]   = Qs[(ty*4+i)*QSTR + d];
            #pragma unroll
            for (int j=0;j<4;j++) kk4[j] = Ks[(tx*4+j)*QSTR + d];
            #pragma unroll
            for (int i=0;i<4;i++)
                #pragma unroll
                for (int j=0;j<4;j++)
                    sacc[i][j] = fmaf(a[i], kk4[j], sacc[i][j]);
        }

        // scale + causal mask + attention_mask -> SS
        #pragma unroll
        for (int i=0;i<4;i++) {
            const int qi = qt*64 + ty*4 + i;
            #pragma unroll
            for (int j=0;j<4;j++) {
                const int kj = kt*64 + tx*4 + j;
                float v = (kj <= qi) ? sacc[i][j]*scale : -10000.0f;
                v += amask[(size_t)b*S_ + kj];
                SS[(ty*4+i)*65 + tx*4+j] = v;
            }
        }
        __syncthreads();

        // online softmax per row (64 rows, 1 thread each)
        if (tid < 64) {
            float mo = mrow[tid];
            float mx = mo;
            #pragma unroll 8
            for (int j=0;j<64;j++) mx = fmaxf(mx, SS[tid*65+j]);
            float al  = __expf(mo - mx);
            float sum = 0.f;
            #pragma unroll 8
            for (int j=0;j<64;j++) {
                float e = __expf(SS[tid*65+j] - mx);
                SS[tid*65+j] = e;
                sum += e;
            }
            mrow[tid] = mx;
            lrow[tid] = lrow[tid]*al + sum;
            arow[tid] = al;
        }
        __syncthreads();

        // rescale accumulators, then O += P @ V
        #pragma unroll
        for (int i=0;i<4;i++) {
            float al = arow[ty*4+i];
            #pragma unroll
            for (int c=0;c<8;c++) o[i][c] *= al;
        }
        #pragma unroll 2
        for (int j=0;j<64;j++) {
            float p[4];
            #pragma unroll
            for (int i=0;i<4;i++) p[i] = SS[(ty*4+i)*65 + j];
            float4 v0 = *(const float4*)&Vs[j*128 + tx*8];
            float4 v1 = *(const float4*)&Vs[j*128 + tx*8 + 4];
            #pragma unroll
            for (int i=0;i<4;i++) {
                o[i][0] = fmaf(p[i], v0.x, o[i][0]);
                o[i][1] = fmaf(p[i], v0.y, o[i][1]);
                o[i][2] = fmaf(p[i], v0.z, o[i][2]);
                o[i][3] = fmaf(p[i], v0.w, o[i][3]);
                o[i][4] = fmaf(p[i], v1.x, o[i][4]);
                o[i][5] = fmaf(p[i], v1.y, o[i][5]);
                o[i][6] = fmaf(p[i], v1.z, o[i][6]);
                o[i][7] = fmaf(p[i], v1.w, o[i][7]);
            }
        }
        __syncthreads();
    }

    // normalize + write: out[b][s][h*HD+d]
    #pragma unroll
    for (int i=0;i<4;i++) {
        const int qi = qt*64 + ty*4 + i;
        const float inv = 1.0f / lrow[ty*4+i];
        float* dst = out + ((size_t)b*S_ + qi)*HID_ + h*HD_ + tx*8;
        float4 w0 = make_float4(o[i][0]*inv, o[i][1]*inv, o[i][2]*inv, o[i][3]*inv);
        float4 w1 = make_float4(o[i][4]*inv, o[i][5]*inv, o[i][6]*inv, o[i][7]*inv);
        *(float4*)dst       = w0;
        *(float4*)(dst + 4) = w1;
    }
}

// ================= launch =================
extern "C" void kernel_launch(void* const* d_in, const int* in_sizes, int n_in,
                              void* d_out, int out_size)
{
    const float* H  = (const float*)d_in[0];
    const float* am = (const float*)d_in[1];
    const float* Wq = (const float*)d_in[2];
    const float* bq = (const float*)d_in[3];
    const float* Wk = (const float*)d_in[4];
    const float* bk = (const float*)d_in[5];
    const float* Wv = (const float*)d_in[6];
    const float* bv = (const float*)d_in[7];
    float* out = (float*)d_out;

    cudaFuncSetAttribute(attn_kernel,
                         cudaFuncAttributeMaxDynamicSharedMemorySize, SMEM_BYTES);

    dim3 ggrid(HID_/GBN, M_/GBM, 3);      // 32 x 64 x 3
    qkv_kernel<<<ggrid, 256>>>(H, Wq, bq, Wk, bk, Wv, bv);

    dim3 agrid(S_/64, NH_, B_);           // 32 x 16 x 2
    attn_kernel<<<agrid, 256, SMEM_BYTES>>>(am, out);
}

// round 3
// speedup vs baseline: 1.7720x; 1.7720x over previous
#include <cuda_runtime.h>
#include <cuda_bf16.h>
#include <math.h>
#include <stdint.h>

#define B_   2
#define S_   2048
#define HID_ 2048
#define NH_  16
#define HD_  128
#define ROT_ 64
#define M_   (B_*S_)          // 4096 rows in QKV GEMM

// ---------------- scratch (no allocations allowed) ----------------
__device__ float g_Q[(size_t)B_*NH_*S_*HD_];
__device__ float g_K[(size_t)B_*NH_*S_*HD_];
__device__ float g_V[(size_t)B_*NH_*S_*HD_];

// ================= helpers =================
__device__ __forceinline__ uint32_t smem_u32(const void* p) {
    return (uint32_t)__cvta_generic_to_shared(p);
}
__device__ __forceinline__ void ldmx4(uint32_t& r0, uint32_t& r1, uint32_t& r2, uint32_t& r3, uint32_t a) {
    asm volatile("ldmatrix.sync.aligned.m8n8.x4.shared.b16 {%0,%1,%2,%3},[%4];"
                 : "=r"(r0), "=r"(r1), "=r"(r2), "=r"(r3) : "r"(a));
}
__device__ __forceinline__ void ldmx2(uint32_t& r0, uint32_t& r1, uint32_t a) {
    asm volatile("ldmatrix.sync.aligned.m8n8.x2.shared.b16 {%0,%1},[%2];"
                 : "=r"(r0), "=r"(r1) : "r"(a));
}
__device__ __forceinline__ void mma_bf16(float* c, const uint32_t* a, const uint32_t* b) {
    asm volatile(
        "mma.sync.aligned.m16n8k16.row.col.f32.bf16.bf16.f32 "
        "{%0,%1,%2,%3},{%4,%5,%6,%7},{%8,%9},{%0,%1,%2,%3};"
        : "+f"(c[0]), "+f"(c[1]), "+f"(c[2]), "+f"(c[3])
        : "r"(a[0]), "r"(a[1]), "r"(a[2]), "r"(a[3]), "r"(b[0]), "r"(b[1]));
}

// ================= QKV projection: bf16x3-split tensor-core GEMM =================
// C[m][n] = sum_k H[m][k] * W[n][k], then bias + RoPE, written to g_{Q,K,V}[b][h][s][d]
#define BM 128
#define BN 64
#define BK 32
#define ASTR 40   // padded bf16 row stride (80 B: conflict-free ldmatrix phases)

__global__ __launch_bounds__(256)
void qkv_kernel(const float* __restrict__ H,
                const float* __restrict__ Wq, const float* __restrict__ bq,
                const float* __restrict__ Wk, const float* __restrict__ bk,
                const float* __restrict__ Wv, const float* __restrict__ bv)
{
    __shared__ __align__(16) __nv_bfloat16 Ahi[BM*ASTR];
    __shared__ __align__(16) __nv_bfloat16 Alo[BM*ASTR];
    __shared__ __align__(16) __nv_bfloat16 Bhi[BN*ASTR];
    __shared__ __align__(16) __nv_bfloat16 Blo[BN*ASTR];

    const int z = blockIdx.z;
    const float* W    = (z==0) ? Wq : (z==1) ? Wk : Wv;
    const float* bias = (z==0) ? bq : (z==1) ? bk : bv;
    float*       Obuf = (z==0) ? g_Q : (z==1) ? g_K : g_V;

    const int tid  = threadIdx.x;
    const int lane = tid & 31;
    const int wid  = tid >> 5;
    const int wm   = wid & 3;        // 4 warps along M
    const int wn   = wid >> 2;       // 2 warps along N
    const int m0   = blockIdx.y * BM;
    const int n0   = blockIdx.x * BN;

    float acc[2][4][4];
    #pragma unroll
    for (int i=0;i<2;i++)
        #pragma unroll
        for (int j=0;j<4;j++)
            #pragma unroll
            for (int e=0;e<4;e++) acc[i][j][e]=0.f;

    // ldmatrix source addresses (fixed per thread, vary by k chunk)
    const int a_row = (lane & 15);
    const int a_col = ((lane >> 4) & 1) * 8;
    const int b_row = (lane & 7);
    const int b_col = ((lane >> 3) & 1) * 8;

    for (int k0 = 0; k0 < HID_; k0 += BK) {
        // ---- load + split A tile (128 x 32 fp32 -> bf16 hi/lo) ----
        #pragma unroll
        for (int it = 0; it < 4; it++) {
            int idx = tid + it*256;          // 0..1023 float4 slots
            int r = idx >> 3;
            int c = (idx & 7) * 4;
            float4 v = *(const float4*)&H[(size_t)(m0+r)*HID_ + k0 + c];
            float xs[4] = {v.x, v.y, v.z, v.w};
            #pragma unroll
            for (int e=0;e<4;e++) {
                __nv_bfloat16 hi = __float2bfloat16(xs[e]);
                __nv_bfloat16 lo = __float2bfloat16(xs[e] - __bfloat162float(hi));
                Ahi[r*ASTR + c + e] = hi;
                Alo[r*ASTR + c + e] = lo;
            }
        }
        // ---- load + split B tile (64 x 32) ----
        #pragma unroll
        for (int it = 0; it < 2; it++) {
            int idx = tid + it*256;          // 0..511
            int r = idx >> 3;
            int c = (idx & 7) * 4;
            float4 v = *(const float4*)&W[(size_t)(n0+r)*HID_ + k0 + c];
            float xs[4] = {v.x, v.y, v.z, v.w};
            #pragma unroll
            for (int e=0;e<4;e++) {
                __nv_bfloat16 hi = __float2bfloat16(xs[e]);
                __nv_bfloat16 lo = __float2bfloat16(xs[e] - __bfloat162float(hi));
                Bhi[r*ASTR + c + e] = hi;
                Blo[r*ASTR + c + e] = lo;
            }
        }
        __syncthreads();

        #pragma unroll
        for (int kk = 0; kk < BK; kk += 16) {
            uint32_t ah[2][4], al[2][4], bh[4][2], bl[4][2];
            #pragma unroll
            for (int mi=0; mi<2; mi++) {
                int row = wm*32 + mi*16 + a_row;
                uint32_t ad = smem_u32(&Ahi[row*ASTR + kk + a_col]);
                ldmx4(ah[mi][0], ah[mi][1], ah[mi][2], ah[mi][3], ad);
                uint32_t ad2 = smem_u32(&Alo[row*ASTR + kk + a_col]);
                ldmx4(al[mi][0], al[mi][1], al[mi][2], al[mi][3], ad2);
            }
            #pragma unroll
            for (int nj=0; nj<4; nj++) {
                int row = wn*32 + nj*8 + b_row;
                uint32_t bd = smem_u32(&Bhi[row*ASTR + kk + b_col]);
                ldmx2(bh[nj][0], bh[nj][1], bd);
                uint32_t bd2 = smem_u32(&Blo[row*ASTR + kk + b_col]);
                ldmx2(bl[nj][0], bl[nj][1], bd2);
            }
            #pragma unroll
            for (int mi=0; mi<2; mi++)
                #pragma unroll
                for (int nj=0; nj<4; nj++) {
                    mma_bf16(acc[mi][nj], ah[mi], bh[nj]);   // hi*hi
                    mma_bf16(acc[mi][nj], ah[mi], bl[nj]);   // hi*lo
                    mma_bf16(acc[mi][nj], al[mi], bh[nj]);   // lo*hi
                }
        }
        __syncthreads();
    }

    // ---- epilogue: bias + RoPE + scatter to [b][h][s][d] ----
    #pragma unroll
    for (int mi=0; mi<2; mi++) {
        #pragma unroll
        for (int nj=0; nj<4; nj++) {
            int cn = n0 + wn*32 + nj*8 + (lane&3)*2;   // even column
            int h  = cn / HD_;
            int d  = cn % HD_;
            float bx = bias[cn], by = bias[cn+1];
            #pragma unroll
            for (int half=0; half<2; half++) {
                int m = m0 + wm*32 + mi*16 + (lane>>2) + half*8;
                int bb = m / S_;
                int s  = m % S_;
                float x = acc[mi][nj][half*2+0] + bx;
                float y = acc[mi][nj][half*2+1] + by;
                if (z < 2 && d < ROT_) {
                    float inv = powf(10000.0f, -(float)d / (float)ROT_);
                    float ang = (float)s * inv;
                    float sn, cs; sincosf(ang, &sn, &cs);
                    float nx = x*cs - y*sn;
                    float ny = y*cs + x*sn;
                    x = nx; y = ny;
                }
                size_t o = (((size_t)bb*NH_ + h)*S_ + s)*HD_ + d;
                Obuf[o]   = x;
                Obuf[o+1] = y;
            }
        }
    }
}

// ================= causal flash attention (fp32) =================
#define QSTR 129                     // padded row stride for Q/K tiles

// shared layout (floats): Qs 64*129 | Ks 64*129 | Vs 64*128 | SS 64*65 | m,l,alpha 3*64
#define SMEM_FLOATS (64*QSTR + 64*QSTR + 64*128 + 64*65 + 3*64)
#define SMEM_BYTES  (SMEM_FLOATS * 4)

__global__ __launch_bounds__(256)
void attn_kernel(const float* __restrict__ amask, float* __restrict__ out)
{
    extern __shared__ __align__(16) float sm[];
    float* Qs   = sm;
    float* Ks   = Qs + 64*QSTR;
    float* Vs   = Ks + 64*QSTR;
    float* SS   = Vs + 64*128;
    float* mrow = SS + 64*65;
    float* lrow = mrow + 64;
    float* arow = lrow + 64;

    const int qt = blockIdx.x, h = blockIdx.y, b = blockIdx.z;
    const float* Q = g_Q + ((size_t)b*NH_ + h)*S_*HD_;
    const float* K = g_K + ((size_t)b*NH_ + h)*S_*HD_;
    const float* V = g_V + ((size_t)b*NH_ + h)*S_*HD_;

    const int tid = threadIdx.x;
    const int tx = tid & 15, ty = tid >> 4;

    #pragma unroll
    for (int it = 0; it < 8; it++) {
        int idx = tid + it*256;
        int r = idx >> 5;
        int c = (idx & 31) * 4;
        float4 v = *(const float4*)&Q[(size_t)(qt*64 + r)*HD_ + c];
        Qs[r*QSTR + c+0]=v.x; Qs[r*QSTR + c+1]=v.y;
        Qs[r*QSTR + c+2]=v.z; Qs[r*QSTR + c+3]=v.w;
    }
    if (tid < 64) { mrow[tid] = -INFINITY; lrow[tid] = 0.f; }

    float o[4][8];
    #pragma unroll
    for (int i=0;i<4;i++)
        #pragma unroll
        for (int c=0;c<8;c++) o[i][c]=0.f;

    __syncthreads();

    const float scale = 0.08838834764831845f;   // 1/sqrt(128)

    for (int kt = 0; kt <= qt; kt++) {
        #pragma unroll
        for (int it = 0; it < 8; it++) {
            int idx = tid + it*256;
            int r = idx >> 5;
            int c = (idx & 31) * 4;
            float4 kv = *(const float4*)&K[(size_t)(kt*64 + r)*HD_ + c];
            Ks[r*QSTR + c+0]=kv.x; Ks[r*QSTR + c+1]=kv.y;
            Ks[r*QSTR + c+2]=kv.z; Ks[r*QSTR + c+3]=kv.w;
            float4 vv = *(const float4*)&V[(size_t)(kt*64 + r)*HD_ + c];
            *(float4*)&Vs[r*128 + c] = vv;
        }
        __syncthreads();

        float sacc[4][4] = {};
        #pragma unroll 4
        for (int d = 0; d < HD_; d++) {
            float a[4], kk4[4];
            #pragma unroll
            for (int i=0;i<4;i++) a[i]   = Qs[(ty*4+i)*QSTR + d];
            #pragma unroll
            for (int j=0;j<4;j++) kk4[j] = Ks[(tx*4+j)*QSTR + d];
            #pragma unroll
            for (int i=0;i<4;i++)
                #pragma unroll
                for (int j=0;j<4;j++)
                    sacc[i][j] = fmaf(a[i], kk4[j], sacc[i][j]);
        }

        #pragma unroll
        for (int i=0;i<4;i++) {
            const int qi = qt*64 + ty*4 + i;
            #pragma unroll
            for (int j=0;j<4;j++) {
                const int kj = kt*64 + tx*4 + j;
                float v = (kj <= qi) ? sacc[i][j]*scale : -10000.0f;
                v += amask[(size_t)b*S_ + kj];
                SS[(ty*4+i)*65 + tx*4+j] = v;
            }
        }
        __syncthreads();

        if (tid < 64) {
            float mo = mrow[tid];
            float mx = mo;
            #pragma unroll 8
            for (int j=0;j<64;j++) mx = fmaxf(mx, SS[tid*65+j]);
            float al  = __expf(mo - mx);
            float sum = 0.f;
            #pragma unroll 8
            for (int j=0;j<64;j++) {
                float e = __expf(SS[tid*65+j] - mx);
                SS[tid*65+j] = e;
                sum += e;
            }
            mrow[tid] = mx;
            lrow[tid] = lrow[tid]*al + sum;
            arow[tid] = al;
        }
        __syncthreads();

        #pragma unroll
        for (int i=0;i<4;i++) {
            float al = arow[ty*4+i];
            #pragma unroll
            for (int c=0;c<8;c++) o[i][c] *= al;
        }
        #pragma unroll 2
        for (int j=0;j<64;j++) {
            float p[4];
            #pragma unroll
            for (int i=0;i<4;i++) p[i] = SS[(ty*4+i)*65 + j];
            float4 v0 = *(const float4*)&Vs[j*128 + tx*8];
            float4 v1 = *(const float4*)&Vs[j*128 + tx*8 + 4];
            #pragma unroll
            for (int i=0;i<4;i++) {
                o[i][0] = fmaf(p[i], v0.x, o[i][0]);
                o[i][1] = fmaf(p[i], v0.y, o[i][1]);
                o[i][2] = fmaf(p[i], v0.z, o[i][2]);
                o[i][3] = fmaf(p[i], v0.w, o[i][3]);
                o[i][4] = fmaf(p[i], v1.x, o[i][4]);
                o[i][5] = fmaf(p[i], v1.y, o[i][5]);
                o[i][6] = fmaf(p[i], v1.z, o[i][6]);
                o[i][7] = fmaf(p[i], v1.w, o[i][7]);
            }
        }
        __syncthreads();
    }

    #pragma unroll
    for (int i=0;i<4;i++) {
        const int qi = qt*64 + ty*4 + i;
        const float inv = 1.0f / lrow[ty*4+i];
        float* dst = out + ((size_t)b*S_ + qi)*HID_ + h*HD_ + tx*8;
        float4 w0 = make_float4(o[i][0]*inv, o[i][1]*inv, o[i][2]*inv, o[i][3]*inv);
        float4 w1 = make_float4(o[i][4]*inv, o[i][5]*inv, o[i][6]*inv, o[i][7]*inv);
        *(float4*)dst       = w0;
        *(float4*)(dst + 4) = w1;
    }
}

// ================= launch =================
extern "C" void kernel_launch(void* const* d_in, const int* in_sizes, int n_in,
                              void* d_out, int out_size)
{
    const float* H  = (const float*)d_in[0];
    const float* am = (const float*)d_in[1];
    const float* Wq = (const float*)d_in[2];
    const float* bq = (const float*)d_in[3];
    const float* Wk = (const float*)d_in[4];
    const float* bk = (const float*)d_in[5];
    const float* Wv = (const float*)d_in[6];
    const float* bv = (const float*)d_in[7];
    float* out = (float*)d_out;

    cudaFuncSetAttribute(attn_kernel,
                         cudaFuncAttributeMaxDynamicSharedMemorySize, SMEM_BYTES);

    dim3 ggrid(HID_/BN, M_/BM, 3);        // 32 x 32 x 3
    qkv_kernel<<<ggrid, 256>>>(H, Wq, bq, Wk, bk, Wv, bv);

    dim3 agrid(S_/64, NH_, B_);           // 32 x 16 x 2
    attn_kernel<<<agrid, 256, SMEM_BYTES>>>(am, out);
}

// round 4
// speedup vs baseline: 3.0387x; 1.7148x over previous
#include <cuda_runtime.h>
#include <cuda_bf16.h>
#include <math.h>
#include <stdint.h>

#define B_   2
#define S_   2048
#define HID_ 2048
#define NH_  16
#define HD_  128
#define ROT_ 64
#define M_   (B_*S_)          // 4096 rows in QKV GEMM

// ---------------- scratch (no allocations allowed) ----------------
__device__ float g_Q[(size_t)B_*NH_*S_*HD_];
__device__ float g_K[(size_t)B_*NH_*S_*HD_];
__device__ float g_V[(size_t)B_*NH_*S_*HD_];
__device__ float2 g_rope[S_*ROT_/2];

// ================= helpers =================
__device__ __forceinline__ uint32_t smem_u32(const void* p) {
    return (uint32_t)__cvta_generic_to_shared(p);
}
__device__ __forceinline__ void ldmx4(uint32_t& r0, uint32_t& r1, uint32_t& r2, uint32_t& r3, uint32_t a) {
    asm volatile("ldmatrix.sync.aligned.m8n8.x4.shared.b16 {%0,%1,%2,%3},[%4];"
                 : "=r"(r0), "=r"(r1), "=r"(r2), "=r"(r3) : "r"(a));
}
__device__ __forceinline__ void ldmx4t(uint32_t& r0, uint32_t& r1, uint32_t& r2, uint32_t& r3, uint32_t a) {
    asm volatile("ldmatrix.sync.aligned.m8n8.x4.trans.shared.b16 {%0,%1,%2,%3},[%4];"
                 : "=r"(r0), "=r"(r1), "=r"(r2), "=r"(r3) : "r"(a));
}
__device__ __forceinline__ void ldmx2(uint32_t& r0, uint32_t& r1, uint32_t a) {
    asm volatile("ldmatrix.sync.aligned.m8n8.x2.shared.b16 {%0,%1},[%2];"
                 : "=r"(r0), "=r"(r1) : "r"(a));
}
__device__ __forceinline__ void mma_bf16(float* c, const uint32_t* a, const uint32_t* b) {
    asm volatile(
        "mma.sync.aligned.m16n8k16.row.col.f32.bf16.bf16.f32 "
        "{%0,%1,%2,%3},{%4,%5,%6,%7},{%8,%9},{%0,%1,%2,%3};"
        : "+f"(c[0]), "+f"(c[1]), "+f"(c[2]), "+f"(c[3])
        : "r"(a[0]), "r"(a[1]), "r"(a[2]), "r"(a[3]), "r"(b[0]), "r"(b[1]));
}
__device__ __forceinline__ uint32_t pack_bf16(float x, float y) {
    __nv_bfloat162 t = __floats2bfloat162_rn(x, y);
    return *(uint32_t*)&t;
}
__device__ __forceinline__ void split_bf16(float x, __nv_bfloat16& hi, __nv_bfloat16& lo) {
    hi = __float2bfloat16(x);
    lo = __float2bfloat16(x - __bfloat162float(hi));
}

// ================= RoPE table init =================
__global__ void rope_init_kernel() {
    int idx = blockIdx.x * 256 + threadIdx.x;
    if (idx < S_*ROT_/2) {
        int s = idx >> 5;        // / (ROT_/2)
        int i = idx & 31;
        float inv = powf(10000.0f, -(float)(2*i) / (float)ROT_);
        float ang = (float)s * inv;
        float sn, cs; sincosf(ang, &sn, &cs);
        g_rope[idx] = make_float2(sn, cs);
    }
}

// ================= QKV projection: bf16x3-split tensor-core GEMM =================
#define BM 128
#define BN 64
#define BK 32
#define ASTR 40

__global__ __launch_bounds__(256)
void qkv_kernel(const float* __restrict__ H,
                const float* __restrict__ Wq, const float* __restrict__ bq,
                const float* __restrict__ Wk, const float* __restrict__ bk,
                const float* __restrict__ Wv, const float* __restrict__ bv)
{
    __shared__ __align__(16) __nv_bfloat16 Ahi[BM*ASTR];
    __shared__ __align__(16) __nv_bfloat16 Alo[BM*ASTR];
    __shared__ __align__(16) __nv_bfloat16 Bhi[BN*ASTR];
    __shared__ __align__(16) __nv_bfloat16 Blo[BN*ASTR];

    const int z = blockIdx.z;
    const float* W    = (z==0) ? Wq : (z==1) ? Wk : Wv;
    const float* bias = (z==0) ? bq : (z==1) ? bk : bv;
    float*       Obuf = (z==0) ? g_Q : (z==1) ? g_K : g_V;

    const int tid  = threadIdx.x;
    const int lane = tid & 31;
    const int wid  = tid >> 5;
    const int wm   = wid & 3;
    const int wn   = wid >> 2;
    const int m0   = blockIdx.y * BM;
    const int n0   = blockIdx.x * BN;

    float acc[2][4][4];
    #pragma unroll
    for (int i=0;i<2;i++)
        #pragma unroll
        for (int j=0;j<4;j++)
            #pragma unroll
            for (int e=0;e<4;e++) acc[i][j][e]=0.f;

    const int a_row = (lane & 15);
    const int a_col = ((lane >> 4) & 1) * 8;
    const int b_row = (lane & 7);
    const int b_col = ((lane >> 3) & 1) * 8;

    for (int k0 = 0; k0 < HID_; k0 += BK) {
        #pragma unroll
        for (int it = 0; it < 4; it++) {
            int idx = tid + it*256;
            int r = idx >> 3;
            int c = (idx & 7) * 4;
            float4 v = *(const float4*)&H[(size_t)(m0+r)*HID_ + k0 + c];
            float xs[4] = {v.x, v.y, v.z, v.w};
            #pragma unroll
            for (int e=0;e<4;e++) {
                __nv_bfloat16 hi, lo; split_bf16(xs[e], hi, lo);
                Ahi[r*ASTR + c + e] = hi;
                Alo[r*ASTR + c + e] = lo;
            }
        }
        #pragma unroll
        for (int it = 0; it < 2; it++) {
            int idx = tid + it*256;
            int r = idx >> 3;
            int c = (idx & 7) * 4;
            float4 v = *(const float4*)&W[(size_t)(n0+r)*HID_ + k0 + c];
            float xs[4] = {v.x, v.y, v.z, v.w};
            #pragma unroll
            for (int e=0;e<4;e++) {
                __nv_bfloat16 hi, lo; split_bf16(xs[e], hi, lo);
                Bhi[r*ASTR + c + e] = hi;
                Blo[r*ASTR + c + e] = lo;
            }
        }
        __syncthreads();

        #pragma unroll
        for (int kk = 0; kk < BK; kk += 16) {
            uint32_t ah[2][4], al[2][4], bh[4][2], bl[4][2];
            #pragma unroll
            for (int mi=0; mi<2; mi++) {
                int row = wm*32 + mi*16 + a_row;
                ldmx4(ah[mi][0], ah[mi][1], ah[mi][2], ah[mi][3],
                      smem_u32(&Ahi[row*ASTR + kk + a_col]));
                ldmx4(al[mi][0], al[mi][1], al[mi][2], al[mi][3],
                      smem_u32(&Alo[row*ASTR + kk + a_col]));
            }
            #pragma unroll
            for (int nj=0; nj<4; nj++) {
                int row = wn*32 + nj*8 + b_row;
                ldmx2(bh[nj][0], bh[nj][1], smem_u32(&Bhi[row*ASTR + kk + b_col]));
                ldmx2(bl[nj][0], bl[nj][1], smem_u32(&Blo[row*ASTR + kk + b_col]));
            }
            #pragma unroll
            for (int mi=0; mi<2; mi++)
                #pragma unroll
                for (int nj=0; nj<4; nj++) {
                    mma_bf16(acc[mi][nj], ah[mi], bh[nj]);
                    mma_bf16(acc[mi][nj], ah[mi], bl[nj]);
                    mma_bf16(acc[mi][nj], al[mi], bh[nj]);
                }
        }
        __syncthreads();
    }

    #pragma unroll
    for (int mi=0; mi<2; mi++) {
        #pragma unroll
        for (int nj=0; nj<4; nj++) {
            int cn = n0 + wn*32 + nj*8 + (lane&3)*2;
            int h  = cn / HD_;
            int d  = cn % HD_;
            float bx = bias[cn], by = bias[cn+1];
            #pragma unroll
            for (int half=0; half<2; half++) {
                int m = m0 + wm*32 + mi*16 + (lane>>2) + half*8;
                int bb = m / S_;
                int s  = m % S_;
                float x = acc[mi][nj][half*2+0] + bx;
                float y = acc[mi][nj][half*2+1] + by;
                if (z < 2 && d < ROT_) {
                    float2 sc = g_rope[s*(ROT_/2) + (d>>1)];
                    float nx = x*sc.y - y*sc.x;
                    float ny = y*sc.y + x*sc.x;
                    x = nx; y = ny;
                }
                size_t o = (((size_t)bb*NH_ + h)*S_ + s)*HD_ + d;
                Obuf[o]   = x;
                Obuf[o+1] = y;
            }
        }
    }
}

// ================= tensor-core causal flash attention (bf16x3 split) =================
#define AQ  128                // queries per CTA
#define AK  64                 // keys per tile
#define KSTR 136               // padded bf16 row stride (272 B)

// smem (bf16): Qhi 128*136 | Qlo | Khi 64*136 | Klo | Vhi | Vlo  + 64 floats amask
#define AT_Q   (AQ*KSTR)
#define AT_K   (AK*KSTR)
#define AT_BF16_TOTAL (2*AT_Q + 4*AT_K)
#define AT_SMEM_BYTES (AT_BF16_TOTAL*2 + 64*4)

__global__ __launch_bounds__(256)
void attn_kernel(const float* __restrict__ amask, float* __restrict__ out)
{
    extern __shared__ __align__(16) char smraw[];
    __nv_bfloat16* Qhi = (__nv_bfloat16*)smraw;
    __nv_bfloat16* Qlo = Qhi + AT_Q;
    __nv_bfloat16* Khi = Qlo + AT_Q;
    __nv_bfloat16* Klo = Khi + AT_K;
    __nv_bfloat16* Vhi = Klo + AT_K;
    __nv_bfloat16* Vlo = Vhi + AT_K;
    float* ms = (float*)(Vlo + AT_K);

    const int qt = (gridDim.x - 1) - blockIdx.x;   // heavy tiles first
    const int h  = blockIdx.y, b = blockIdx.z;
    const float* Qg = g_Q + ((size_t)b*NH_ + h)*S_*HD_;
    const float* Kg = g_K + ((size_t)b*NH_ + h)*S_*HD_;
    const float* Vg = g_V + ((size_t)b*NH_ + h)*S_*HD_;

    const int tid  = threadIdx.x;
    const int lane = tid & 31;
    const int w    = tid >> 5;         // 8 warps, 16 rows each
    const int qbase = qt*AQ + w*16;    // global query row of warp row 0

    // ---- load + split Q tile (128 x 128) ----
    #pragma unroll
    for (int it = 0; it < 16; it++) {
        int idx = tid + it*256;         // 0..4095 float4 slots
        int r = idx >> 5;
        int c = (idx & 31) * 4;
        float4 v = *(const float4*)&Qg[(size_t)(qt*AQ + r)*HD_ + c];
        float xs[4] = {v.x, v.y, v.z, v.w};
        #pragma unroll
        for (int e=0;e<4;e++) {
            __nv_bfloat16 hi, lo; split_bf16(xs[e], hi, lo);
            Qhi[r*KSTR + c + e] = hi;
            Qlo[r*KSTR + c + e] = lo;
        }
    }

    float o[16][4];
    #pragma unroll
    for (int nt=0; nt<16; nt++)
        #pragma unroll
        for (int e=0;e<4;e++) o[nt][e]=0.f;

    float m0 = -INFINITY, m1 = -INFINITY, l0 = 0.f, l1 = 0.f;
    const float scale = 0.08838834764831845f;   // 1/sqrt(128)

    // ldmatrix per-lane address components
    const int qa_row = lane & 15;
    const int qa_col = (lane >> 4) * 8;
    const int kb_key = (lane & 7) + ((lane >> 4) << 3);
    const int kb_col = ((lane >> 3) & 1) * 8;
    const int vb_key = (lane & 7) + (((lane >> 3) & 1) << 3);
    const int vb_col = (lane >> 4) * 8;

    const int ktmax = 2*qt + 1;
    for (int kt = 0; kt <= ktmax; kt++) {
        __syncthreads();   // previous compute done (also covers Q on iter 0)

        // ---- load + split K,V tiles (64 x 128 each) ----
        #pragma unroll
        for (int it = 0; it < 8; it++) {
            int idx = tid + it*256;
            int r = idx >> 5;
            int c = (idx & 31) * 4;
            float4 kv = *(const float4*)&Kg[(size_t)(kt*AK + r)*HD_ + c];
            float ks4[4] = {kv.x, kv.y, kv.z, kv.w};
            float4 vv = *(const float4*)&Vg[(size_t)(kt*AK + r)*HD_ + c];
            float vs4[4] = {vv.x, vv.y, vv.z, vv.w};
            #pragma unroll
            for (int e=0;e<4;e++) {
                __nv_bfloat16 hi, lo;
                split_bf16(ks4[e], hi, lo);
                Khi[r*KSTR + c + e] = hi; Klo[r*KSTR + c + e] = lo;
                split_bf16(vs4[e], hi, lo);
                Vhi[r*KSTR + c + e] = hi; Vlo[r*KSTR + c + e] = lo;
            }
        }
        if (tid < 64) ms[tid] = amask[(size_t)b*S_ + kt*AK + tid];
        __syncthreads();

        // ---- S = Q K^T (fp32 frags, bf16x3) ----
        float s[8][4];
        #pragma unroll
        for (int nt=0; nt<8; nt++)
            #pragma unroll
            for (int e=0;e<4;e++) s[nt][e]=0.f;

        #pragma unroll
        for (int ks = 0; ks < 8; ks++) {
            const int d0 = ks*16;
            uint32_t ah[4], al[4];
            ldmx4(ah[0],ah[1],ah[2],ah[3], smem_u32(&Qhi[(w*16+qa_row)*KSTR + d0 + qa_col]));
            ldmx4(al[0],al[1],al[2],al[3], smem_u32(&Qlo[(w*16+qa_row)*KSTR + d0 + qa_col]));
            #pragma unroll
            for (int ntp = 0; ntp < 4; ntp++) {
                const int n0 = ntp*16;
                uint32_t bh[4], bl[4];
                ldmx4(bh[0],bh[1],bh[2],bh[3], smem_u32(&Khi[(n0+kb_key)*KSTR + d0 + kb_col]));
                ldmx4(bl[0],bl[1],bl[2],bl[3], smem_u32(&Klo[(n0+kb_key)*KSTR + d0 + kb_col]));
                mma_bf16(s[ntp*2],   ah, &bh[0]);
                mma_bf16(s[ntp*2],   ah, &bl[0]);
                mma_bf16(s[ntp*2],   al, &bh[0]);
                mma_bf16(s[ntp*2+1], ah, &bh[2]);
                mma_bf16(s[ntp*2+1], ah, &bl[2]);
                mma_bf16(s[ntp*2+1], al, &bh[2]);
            }
        }

        // ---- scale + causal + amask ----
        const int qi0 = qbase + (lane>>2);
        const int qi1 = qi0 + 8;
        #pragma unroll
        for (int nt=0; nt<8; nt++) {
            const int kc = kt*AK + nt*8 + (lane&3)*2;
            const float am0 = ms[nt*8 + (lane&3)*2];
            const float am1 = ms[nt*8 + (lane&3)*2 + 1];
            s[nt][0] = ((kc   <= qi0) ? s[nt][0]*scale : -10000.f) + am0;
            s[nt][1] = ((kc+1 <= qi0) ? s[nt][1]*scale : -10000.f) + am1;
            s[nt][2] = ((kc   <= qi1) ? s[nt][2]*scale : -10000.f) + am0;
            s[nt][3] = ((kc+1 <= qi1) ? s[nt][3]*scale : -10000.f) + am1;
        }

        // ---- online softmax (rows qi0, qi1 per 4-lane group) ----
        float mx0 = -INFINITY, mx1 = -INFINITY;
        #pragma unroll
        for (int nt=0; nt<8; nt++) {
            mx0 = fmaxf(mx0, fmaxf(s[nt][0], s[nt][1]));
            mx1 = fmaxf(mx1, fmaxf(s[nt][2], s[nt][3]));
        }
        mx0 = fmaxf(mx0, __shfl_xor_sync(0xffffffffu, mx0, 1));
        mx0 = fmaxf(mx0, __shfl_xor_sync(0xffffffffu, mx0, 2));
        mx1 = fmaxf(mx1, __shfl_xor_sync(0xffffffffu, mx1, 1));
        mx1 = fmaxf(mx1, __shfl_xor_sync(0xffffffffu, mx1, 2));
        const float mn0 = fmaxf(m0, mx0), mn1 = fmaxf(m1, mx1);
        const float al0 = __expf(m0 - mn0), al1 = __expf(m1 - mn1);
        m0 = mn0; m1 = mn1;

        float sum0 = 0.f, sum1 = 0.f;
        #pragma unroll
        for (int nt=0; nt<8; nt++) {
            s[nt][0] = __expf(s[nt][0] - mn0);
            s[nt][1] = __expf(s[nt][1] - mn0);
            s[nt][2] = __expf(s[nt][2] - mn1);
            s[nt][3] = __expf(s[nt][3] - mn1);
            sum0 += s[nt][0] + s[nt][1];
            sum1 += s[nt][2] + s[nt][3];
        }
        sum0 += __shfl_xor_sync(0xffffffffu, sum0, 1);
        sum0 += __shfl_xor_sync(0xffffffffu, sum0, 2);
        sum1 += __shfl_xor_sync(0xffffffffu, sum1, 1);
        sum1 += __shfl_xor_sync(0xffffffffu, sum1, 2);
        l0 = l0*al0 + sum0;
        l1 = l1*al1 + sum1;

        // ---- rescale O ----
        #pragma unroll
        for (int nt=0; nt<16; nt++) {
            o[nt][0] *= al0; o[nt][1] *= al0;
            o[nt][2] *= al1; o[nt][3] *= al1;
        }

        // ---- O += P V (bf16x3 split; P frags built in registers) ----
        #pragma unroll
        for (int ks = 0; ks < 4; ks++) {
            const int t0 = 2*ks, t1 = 2*ks+1;
            uint32_t pa_hi[4], pa_lo[4];
            {
                float v00 = s[t0][0], v01 = s[t0][1], v02 = s[t0][2], v03 = s[t0][3];
                float v10 = s[t1][0], v11 = s[t1][1], v12 = s[t1][2], v13 = s[t1][3];
                float h00 = __bfloat162float(__float2bfloat16(v00));
                float h01 = __bfloat162float(__float2bfloat16(v01));
                float h02 = __bfloat162float(__float2bfloat16(v02));
                float h03 = __bfloat162float(__float2bfloat16(v03));
                float h10 = __bfloat162float(__float2bfloat16(v10));
                float h11 = __bfloat162float(__float2bfloat16(v11));
                float h12 = __bfloat162float(__float2bfloat16(v12));
                float h13 = __bfloat162float(__float2bfloat16(v13));
                pa_hi[0] = pack_bf16(h00, h01);
                pa_hi[1] = pack_bf16(h02, h03);
                pa_hi[2] = pack_bf16(h10, h11);
                pa_hi[3] = pack_bf16(h12, h13);
                pa_lo[0] = pack_bf16(v00-h00, v01-h01);
                pa_lo[1] = pack_bf16(v02-h02, v03-h03);
                pa_lo[2] = pack_bf16(v10-h10, v11-h11);
                pa_lo[3] = pack_bf16(v12-h12, v13-h13);
            }
            const int k0 = ks*16;
            #pragma unroll
            for (int ntp = 0; ntp < 8; ntp++) {
                const int n0 = ntp*16;
                uint32_t vh[4], vl[4];
                ldmx4t(vh[0],vh[1],vh[2],vh[3], smem_u32(&Vhi[(k0+vb_key)*KSTR + n0 + vb_col]));
                ldmx4t(vl[0],vl[1],vl[2],vl[3], smem_u32(&Vlo[(k0+vb_key)*KSTR + n0 + vb_col]));
                mma_bf16(o[ntp*2],   pa_hi, &vh[0]);
                mma_bf16(o[ntp*2],   pa_hi, &vl[0]);
                mma_bf16(o[ntp*2],   pa_lo, &vh[0]);
                mma_bf16(o[ntp*2+1], pa_hi, &vh[2]);
                mma_bf16(o[ntp*2+1], pa_hi, &vl[2]);
                mma_bf16(o[ntp*2+1], pa_lo, &vh[2]);
            }
        }
    }

    // ---- normalize + write out[b][s][h*HD+d] ----
    const float inv0 = 1.0f / l0;
    const float inv1 = 1.0f / l1;
    const int r0 = qbase + (lane>>2);
    const int r1 = r0 + 8;
    #pragma unroll
    for (int nt=0; nt<16; nt++) {
        const int col = h*HD_ + nt*8 + (lane&3)*2;
        float2 w0 = make_float2(o[nt][0]*inv0, o[nt][1]*inv0);
        float2 w1 = make_float2(o[nt][2]*inv1, o[nt][3]*inv1);
        *(float2*)&out[(size_t)(b*S_ + r0)*HID_ + col] = w0;
        *(float2*)&out[(size_t)(b*S_ + r1)*HID_ + col] = w1;
    }
}

// ================= launch =================
extern "C" void kernel_launch(void* const* d_in, const int* in_sizes, int n_in,
                              void* d_out, int out_size)
{
    const float* H  = (const float*)d_in[0];
    const float* am = (const float*)d_in[1];
    const float* Wq = (const float*)d_in[2];
    const float* bq = (const float*)d_in[3];
    const float* Wk = (const float*)d_in[4];
    const float* bk = (const float*)d_in[5];
    const float* Wv = (const float*)d_in[6];
    const float* bv = (const float*)d_in[7];
    float* out = (float*)d_out;

    cudaFuncSetAttribute(attn_kernel,
                         cudaFuncAttributeMaxDynamicSharedMemorySize, AT_SMEM_BYTES);

    rope_init_kernel<<<(S_*ROT_/2 + 255)/256, 256>>>();

    dim3 ggrid(HID_/BN, M_/BM, 3);        // 32 x 32 x 3
    qkv_kernel<<<ggrid, 256>>>(H, Wq, bq, Wk, bk, Wv, bv);

    dim3 agrid(S_/AQ, NH_, B_);           // 16 x 16 x 2
    attn_kernel<<<agrid, 256, AT_SMEM_BYTES>>>(am, out);
}

// round 9
// speedup vs baseline: 4.6443x; 1.5284x over previous
#include <cuda_runtime.h>
#include <cuda_fp16.h>
#include <math.h>
#include <stdint.h>

#define B_   2
#define S_   2048
#define HID_ 2048
#define NH_  16
#define HD_  128
#define ROT_ 64
#define M_   (B_*S_)          // 4096 rows in QKV GEMM

// ---------------- scratch (no allocations allowed) ----------------
__device__ __align__(128) __half g_Hh [(size_t)M_*HID_];
__device__ __align__(128) __half g_Whi[3][(size_t)HID_*HID_];
__device__ __align__(128) __half g_Wlo[3][(size_t)HID_*HID_];
__device__ __align__(128) __half g_Qh [(size_t)B_*NH_*S_*HD_];
__device__ __align__(128) __half g_Khi[(size_t)B_*NH_*S_*HD_];
__device__ __align__(128) __half g_Klo[(size_t)B_*NH_*S_*HD_];
__device__ __align__(128) __half g_Vhi[(size_t)B_*NH_*S_*HD_];
__device__ __align__(128) __half g_Vlo[(size_t)B_*NH_*S_*HD_];
__device__ __align__(128) float2 g_rope[S_*ROT_/2];

// ================= helpers =================
__device__ __forceinline__ uint32_t smem_u32(const void* p) {
    return (uint32_t)__cvta_generic_to_shared(p);
}
__device__ __forceinline__ void split_f16(float x, __half& hi, __half& lo) {
    hi = __float2half_rn(x);
    lo = __float2half_rn(x - __half2float(hi));
}
__device__ __forceinline__ uint32_t pack_h2(float x, float y) {
    __half2 t = __floats2half2_rn(x, y);
    return *(uint32_t*)&t;
}
__device__ __forceinline__ void ldmx4(uint32_t& r0, uint32_t& r1, uint32_t& r2, uint32_t& r3, uint32_t a) {
    asm volatile("ldmatrix.sync.aligned.m8n8.x4.shared.b16 {%0,%1,%2,%3},[%4];"
                 : "=r"(r0), "=r"(r1), "=r"(r2), "=r"(r3) : "r"(a));
}
__device__ __forceinline__ void ldmx4t(uint32_t& r0, uint32_t& r1, uint32_t& r2, uint32_t& r3, uint32_t a) {
    asm volatile("ldmatrix.sync.aligned.m8n8.x4.trans.shared.b16 {%0,%1,%2,%3},[%4];"
                 : "=r"(r0), "=r"(r1), "=r"(r2), "=r"(r3) : "r"(a));
}
__device__ __forceinline__ void ldmx2(uint32_t& r0, uint32_t& r1, uint32_t a) {
    asm volatile("ldmatrix.sync.aligned.m8n8.x2.shared.b16 {%0,%1},[%2];"
                 : "=r"(r0), "=r"(r1) : "r"(a));
}
__device__ __forceinline__ void mma_fp16(float* c, const uint32_t* a, const uint32_t* b) {
    asm volatile(
        "mma.sync.aligned.m16n8k16.row.col.f32.f16.f16.f32 "
        "{%0,%1,%2,%3},{%4,%5,%6,%7},{%8,%9},{%0,%1,%2,%3};"
        : "+f"(c[0]), "+f"(c[1]), "+f"(c[2]), "+f"(c[3])
        : "r"(a[0]), "r"(a[1]), "r"(a[2]), "r"(a[3]), "r"(b[0]), "r"(b[1]));
}
__device__ __forceinline__ void cpasync16(uint32_t dst, const void* src) {
    asm volatile("cp.async.cg.shared.global [%0], [%1], 16;" :: "r"(dst), "l"(src));
}
__device__ __forceinline__ void cp_commit() { asm volatile("cp.async.commit_group;" ::: "memory"); }
template<int N> __device__ __forceinline__ void cp_wait() {
    asm volatile("cp.async.wait_group %0;" :: "n"(N) : "memory");
}

// ================= RoPE table init =================
__global__ void rope_init_kernel() {
    int idx = blockIdx.x * 256 + threadIdx.x;
    if (idx < S_*ROT_/2) {
        int s = idx >> 5;
        int i = idx & 31;
        float inv = powf(10000.0f, -(float)(2*i) / (float)ROT_);
        float ang = (float)s * inv;
        float sn, cs; sincosf(ang, &sn, &cs);
        g_rope[idx] = make_float2(sn, cs);
    }
}

// ================= fp32 -> fp16 planes =================
// t==0: H -> single fp16 plane.  t=1..3: W -> hi/lo fp16 planes.
__global__ __launch_bounds__(256)
void convert_kernel(const float* __restrict__ H,
                    const float* __restrict__ Wq,
                    const float* __restrict__ Wk,
                    const float* __restrict__ Wv)
{
    const int t = blockIdx.y;
    const float* src = (t==0) ? H : (t==1) ? Wq : (t==2) ? Wk : Wv;
    const size_t n4 = ((t==0) ? (size_t)M_*HID_ : (size_t)HID_*HID_) / 4;
    size_t i = (size_t)blockIdx.x * 256 + threadIdx.x;
    if (i >= n4) return;
    float4 v = *(const float4*)(src + i*4);
    if (t == 0) {
        uint2 p = make_uint2(pack_h2(v.x, v.y), pack_h2(v.z, v.w));
        *(uint2*)(g_Hh + i*4) = p;
    } else {
        __half h0,l0,h1,l1,h2,l2,h3,l3;
        split_f16(v.x,h0,l0); split_f16(v.y,h1,l1);
        split_f16(v.z,h2,l2); split_f16(v.w,h3,l3);
        uint2 ph = make_uint2(pack_h2(__half2float(h0),__half2float(h1)),
                              pack_h2(__half2float(h2),__half2float(h3)));
        uint2 pl = make_uint2(pack_h2(__half2float(l0),__half2float(l1)),
                              pack_h2(__half2float(l2),__half2float(l3)));
        *(uint2*)(g_Whi[t-1] + i*4) = ph;
        *(uint2*)(g_Wlo[t-1] + i*4) = pl;
    }
}

// ================= QKV projection: fp16x2-split mma GEMM =================
// C[m][n] = sum_k H[m][k] * W[n][k]; epilogue bias + RoPE, writes fp16 planes.
#define BM 128
#define BN 64
#define BK 32
#define NKS (HID_/BK)          // 64
#define QASTR 40               // padded half row stride (80 B)

__global__ __launch_bounds__(256)
void qkv_kernel(const float* __restrict__ bq,
                const float* __restrict__ bk,
                const float* __restrict__ bv)
{
    __shared__ __align__(16) __half sA [2][BM*QASTR];
    __shared__ __align__(16) __half sBh[2][BN*QASTR];
    __shared__ __align__(16) __half sBl[2][BN*QASTR];

    const int z  = blockIdx.z;
    const float* bias = (z==0) ? bq : (z==1) ? bk : bv;
    const __half* Whi_ = g_Whi[z];
    const __half* Wlo_ = g_Wlo[z];

    const int tid  = threadIdx.x;
    const int lane = tid & 31;
    const int wid  = tid >> 5;
    const int wm   = wid & 3;        // 4 warps along M (32 rows each)
    const int wn   = wid >> 2;       // 2 warps along N (32 cols each)
    const int m0   = blockIdx.y * BM;
    const int n0   = blockIdx.x * BN;

    const uint32_t aB[2]  = { smem_u32(&sA [0][0]), smem_u32(&sA [1][0]) };
    const uint32_t bhB[2] = { smem_u32(&sBh[0][0]), smem_u32(&sBh[1][0]) };
    const uint32_t blB[2] = { smem_u32(&sBl[0][0]), smem_u32(&sBl[1][0]) };

    float acc[2][4][4];
    #pragma unroll
    for (int i=0;i<2;i++)
        #pragma unroll
        for (int j=0;j<4;j++)
            #pragma unroll
            for (int e=0;e<4;e++) acc[i][j][e]=0.f;

    const int a_row = lane & 15;
    const int a_col = ((lane >> 4) & 1) * 8;
    const int b_row = lane & 7;
    const int b_col = ((lane >> 3) & 1) * 8;

    // ---- stage loader (cp.async) ----
    auto load_stage = [&](int st, int k0) {
        #pragma unroll
        for (int it = 0; it < 2; it++) {          // A: 128 rows x 4 chunks of 16B
            int i = tid + it*256;
            int r = i >> 2, c = i & 3;
            cpasync16(aB[st] + r*80 + c*16, g_Hh + (size_t)(m0 + r)*HID_ + k0 + c*8);
        }
        {                                          // Bhi: 64 rows x 4 chunks
            int r = tid >> 2, c = tid & 3;
            cpasync16(bhB[st] + r*80 + c*16, Whi_ + (size_t)(n0 + r)*HID_ + k0 + c*8);
            cpasync16(blB[st] + r*80 + c*16, Wlo_ + (size_t)(n0 + r)*HID_ + k0 + c*8);
        }
        cp_commit();
    };

    load_stage(0, 0);

    for (int ks = 0; ks < NKS; ks++) {
        const int cur = ks & 1;
        if (ks + 1 < NKS) {
            load_stage(cur ^ 1, (ks+1)*BK);
            cp_wait<1>();
        } else {
            cp_wait<0>();
        }
        __syncthreads();

        #pragma unroll
        for (int k16 = 0; k16 < BK; k16 += 16) {
            uint32_t a[2][4], bh[4][2], bl[4][2];
            #pragma unroll
            for (int mi=0; mi<2; mi++) {
                int row = wm*32 + mi*16 + a_row;
                ldmx4(a[mi][0],a[mi][1],a[mi][2],a[mi][3],
                      aB[cur] + (row*QASTR + k16 + a_col)*2);
            }
            #pragma unroll
            for (int nj=0; nj<4; nj++) {
                int row = wn*32 + nj*8 + b_row;
                ldmx2(bh[nj][0], bh[nj][1], bhB[cur] + (row*QASTR + k16 + b_col)*2);
                ldmx2(bl[nj][0], bl[nj][1], blB[cur] + (row*QASTR + k16 + b_col)*2);
            }
            #pragma unroll
            for (int mi=0; mi<2; mi++)
                #pragma unroll
                for (int nj=0; nj<4; nj++) {
                    mma_fp16(acc[mi][nj], a[mi], bh[nj]);
                    mma_fp16(acc[mi][nj], a[mi], bl[nj]);
                }
        }
        __syncthreads();
    }

    // ---- epilogue: bias + RoPE -> fp16 planes [b][h][s][d] ----
    #pragma unroll
    for (int mi=0; mi<2; mi++) {
        #pragma unroll
        for (int nj=0; nj<4; nj++) {
            const int n  = n0 + wn*32 + nj*8 + (lane&3)*2;   // even global col
            const int hh = n >> 7;
            const int d  = n & 127;
            const float bx = __ldg(&bias[n]), by = __ldg(&bias[n+1]);
            #pragma unroll
            for (int hf=0; hf<2; hf++) {
                const int m  = m0 + wm*32 + mi*16 + (lane>>2) + hf*8;
                const int bb = m >> 11;          // / S_
                const int s  = m & 2047;
                float x = acc[mi][nj][hf*2+0] + bx;
                float y = acc[mi][nj][hf*2+1] + by;
                if (z < 2 && d < ROT_) {
                    float2 sc = g_rope[s*(ROT_/2) + (d>>1)];
                    float nx = x*sc.y - y*sc.x;
                    float ny = y*sc.y + x*sc.x;
                    x = nx; y = ny;
                }
                const size_t o = (((size_t)bb*NH_ + hh)*S_ + s)*(size_t)HD_ + d;
                if (z == 0) {
                    *(uint32_t*)(g_Qh + o) = pack_h2(x, y);
                } else {
                    __half xh,xl,yh,yl;
                    split_f16(x, xh, xl);
                    split_f16(y, yh, yl);
                    __half* Phi = (z==1) ? g_Khi : g_Vhi;
                    __half* Plo = (z==1) ? g_Klo : g_Vlo;
                    *(uint32_t*)(Phi + o) = pack_h2(__half2float(xh), __half2float(yh));
                    *(uint32_t*)(Plo + o) = pack_h2(__half2float(xl), __half2float(yl));
                }
            }
        }
    }
}

// ================= causal flash attention (fp16x2 split) =================
#define AQ  128
#define AK  64
#define KSTR 136     // padded half row stride (272 B) — conflict-free ldmatrix

#define AT_Q (AQ*KSTR)
#define AT_K (AK*KSTR)
#define AT_SMEM_BYTES ((AT_Q + 4*AT_K)*2 + 64*4)

__global__ __launch_bounds__(256)
void attn_kernel(const float* __restrict__ amask, float* __restrict__ out)
{
    extern __shared__ __align__(16) char smraw[];
    __half* Qs = (__half*)smraw;
    __half* Kh = Qs + AT_Q;
    __half* Kl = Kh + AT_K;
    __half* Vh = Kl + AT_K;
    __half* Vl = Vh + AT_K;
    float* ms  = (float*)(Vl + AT_K);

    const int qt = (gridDim.x - 1) - blockIdx.x;   // heavy tiles first
    const int h  = blockIdx.y, b = blockIdx.z;
    const size_t hoff = ((size_t)b*NH_ + h)*S_*HD_;
    const __half* Qg  = g_Qh  + hoff;
    const __half* Khg = g_Khi + hoff;
    const __half* Klg = g_Klo + hoff;
    const __half* Vhg = g_Vhi + hoff;
    const __half* Vlg = g_Vlo + hoff;

    const int tid  = threadIdx.x;
    const int lane = tid & 31;
    const int w    = tid >> 5;         // 8 warps, 16 query rows each
    const int qbase = qt*AQ + w*16;

    // ---- load Q tile (128 x 128 fp16) ----
    #pragma unroll
    for (int it = 0; it < 8; it++) {
        int idx = tid + it*256;          // 2048 chunks of 8 halves
        int r = idx >> 4;
        int c = (idx & 15) * 8;
        *(float4*)&Qs[r*KSTR + c] = *(const float4*)&Qg[(size_t)(qt*AQ + r)*HD_ + c];
    }

    float o[16][4];
    #pragma unroll
    for (int nt=0; nt<16; nt++)
        #pragma unroll
        for (int e=0;e<4;e++) o[nt][e]=0.f;

    float m0 = -INFINITY, m1 = -INFINITY, l0 = 0.f, l1 = 0.f;
    const float scale = 0.08838834764831845f;   // 1/sqrt(128)

    const int qa_row = lane & 15;
    const int qa_col = (lane >> 4) * 8;
    const int kb_key = (lane & 7) + ((lane >> 4) << 3);
    const int kb_col = ((lane >> 3) & 1) * 8;
    const int vb_key = (lane & 7) + (((lane >> 3) & 1) << 3);
    const int vb_col = (lane >> 4) * 8;

    const int ktmax = 2*qt + 1;
    for (int kt = 0; kt <= ktmax; kt++) {
        __syncthreads();   // previous compute done (covers Q load on iter 0)

        #pragma unroll
        for (int it = 0; it < 4; it++) {
            int idx = tid + it*256;        // 1024 chunks of 8 halves
            int r = idx >> 4;
            int c = (idx & 15) * 8;
            const size_t so = (size_t)(kt*AK + r)*HD_ + c;
            *(float4*)&Kh[r*KSTR + c] = *(const float4*)&Khg[so];
            *(float4*)&Kl[r*KSTR + c] = *(const float4*)&Klg[so];
            *(float4*)&Vh[r*KSTR + c] = *(const float4*)&Vhg[so];
            *(float4*)&Vl[r*KSTR + c] = *(const float4*)&Vlg[so];
        }
        if (tid < 64) ms[tid] = amask[(size_t)b*S_ + kt*AK + tid];
        __syncthreads();

        // ---- S = Q K^T (Q single, K hi+lo) ----
        float s[8][4];
        #pragma unroll
        for (int nt=0; nt<8; nt++)
            #pragma unroll
            for (int e=0;e<4;e++) s[nt][e]=0.f;

        #pragma unroll
        for (int ks = 0; ks < 8; ks++) {
            const int d0 = ks*16;
            uint32_t a[4];
            ldmx4(a[0],a[1],a[2],a[3],
                  smem_u32(&Qs[(w*16+qa_row)*KSTR + d0 + qa_col]));
            #pragma unroll
            for (int ntp = 0; ntp < 4; ntp++) {
                const int n0 = ntp*16;
                uint32_t bh[4], bl[4];
                ldmx4(bh[0],bh[1],bh[2],bh[3], smem_u32(&Kh[(n0+kb_key)*KSTR + d0 + kb_col]));
                ldmx4(bl[0],bl[1],bl[2],bl[3], smem_u32(&Kl[(n0+kb_key)*KSTR + d0 + kb_col]));
                mma_fp16(s[ntp*2],   a, &bh[0]);
                mma_fp16(s[ntp*2],   a, &bl[0]);
                mma_fp16(s[ntp*2+1], a, &bh[2]);
                mma_fp16(s[ntp*2+1], a, &bl[2]);
            }
        }

        // ---- scale + causal + amask ----
        const int qi0 = qbase + (lane>>2);
        const int qi1 = qi0 + 8;
        #pragma unroll
        for (int nt=0; nt<8; nt++) {
            const int kc = kt*AK + nt*8 + (lane&3)*2;
            const float am0 = ms[nt*8 + (lane&3)*2];
            const float am1 = ms[nt*8 + (lane&3)*2 + 1];
            s[nt][0] = ((kc   <= qi0) ? s[nt][0]*scale : -10000.f) + am0;
            s[nt][1] = ((kc+1 <= qi0) ? s[nt][1]*scale : -10000.f) + am1;
            s[nt][2] = ((kc   <= qi1) ? s[nt][2]*scale : -10000.f) + am0;
            s[nt][3] = ((kc+1 <= qi1) ? s[nt][3]*scale : -10000.f) + am1;
        }

        // ---- online softmax (rows qi0, qi1 per 4-lane group) ----
        float mx0 = -INFINITY, mx1 = -INFINITY;
        #pragma unroll
        for (int nt=0; nt<8; nt++) {
            mx0 = fmaxf(mx0, fmaxf(s[nt][0], s[nt][1]));
            mx1 = fmaxf(mx1, fmaxf(s[nt][2], s[nt][3]));
        }
        mx0 = fmaxf(mx0, __shfl_xor_sync(0xffffffffu, mx0, 1));
        mx0 = fmaxf(mx0, __shfl_xor_sync(0xffffffffu, mx0, 2));
        mx1 = fmaxf(mx1, __shfl_xor_sync(0xffffffffu, mx1, 1));
        mx1 = fmaxf(mx1, __shfl_xor_sync(0xffffffffu, mx1, 2));
        const float mn0 = fmaxf(m0, mx0), mn1 = fmaxf(m1, mx1);
        const float al0 = __expf(m0 - mn0), al1 = __expf(m1 - mn1);
        m0 = mn0; m1 = mn1;

        float sum0 = 0.f, sum1 = 0.f;
        #pragma unroll
        for (int nt=0; nt<8; nt++) {
            s[nt][0] = __expf(s[nt][0] - mn0);
            s[nt][1] = __expf(s[nt][1] - mn0);
            s[nt][2] = __expf(s[nt][2] - mn1);
            s[nt][3] = __expf(s[nt][3] - mn1);
            sum0 += s[nt][0] + s[nt][1];
            sum1 += s[nt][2] + s[nt][3];
        }
        sum0 += __shfl_xor_sync(0xffffffffu, sum0, 1);
        sum0 += __shfl_xor_sync(0xffffffffu, sum0, 2);
        sum1 += __shfl_xor_sync(0xffffffffu, sum1, 1);
        sum1 += __shfl_xor_sync(0xffffffffu, sum1, 2);
        l0 = l0*al0 + sum0;
        l1 = l1*al1 + sum1;

        // ---- rescale O ----
        #pragma unroll
        for (int nt=0; nt<16; nt++) {
            o[nt][0] *= al0; o[nt][1] *= al0;
            o[nt][2] *= al1; o[nt][3] *= al1;
        }

        // ---- O += P V (P single fp16, V hi+lo) ----
        #pragma unroll
        for (int ks = 0; ks < 4; ks++) {
            const int t0 = 2*ks, t1 = 2*ks+1;
            uint32_t pa[4];
            pa[0] = pack_h2(s[t0][0], s[t0][1]);
            pa[1] = pack_h2(s[t0][2], s[t0][3]);
            pa[2] = pack_h2(s[t1][0], s[t1][1]);
            pa[3] = pack_h2(s[t1][2], s[t1][3]);
            const int k0 = ks*16;
            #pragma unroll
            for (int ntp = 0; ntp < 8; ntp++) {
                const int n0 = ntp*16;
                uint32_t vh[4], vl[4];
                ldmx4t(vh[0],vh[1],vh[2],vh[3], smem_u32(&Vh[(k0+vb_key)*KSTR + n0 + vb_col]));
                ldmx4t(vl[0],vl[1],vl[2],vl[3], smem_u32(&Vl[(k0+vb_key)*KSTR + n0 + vb_col]));
                mma_fp16(o[ntp*2],   pa, &vh[0]);
                mma_fp16(o[ntp*2],   pa, &vl[0]);
                mma_fp16(o[ntp*2+1], pa, &vh[2]);
                mma_fp16(o[ntp*2+1], pa, &vl[2]);
            }
        }
    }

    // ---- normalize + write out[b][s][h*HD+d] ----
    const float inv0 = 1.0f / l0;
    const float inv1 = 1.0f / l1;
    const int r0 = qbase + (lane>>2);
    const int r1 = r0 + 8;
    #pragma unroll
    for (int nt=0; nt<16; nt++) {
        const int col = h*HD_ + nt*8 + (lane&3)*2;
        float2 w0 = make_float2(o[nt][0]*inv0, o[nt][1]*inv0);
        float2 w1 = make_float2(o[nt][2]*inv1, o[nt][3]*inv1);
        *(float2*)&out[(size_t)(b*S_ + r0)*HID_ + col] = w0;
        *(float2*)&out[(size_t)(b*S_ + r1)*HID_ + col] = w1;
    }
}

// ================= launch =================
extern "C" void kernel_launch(void* const* d_in, const int* in_sizes, int n_in,
                              void* d_out, int out_size)
{
    const float* H  = (const float*)d_in[0];
    const float* am = (const float*)d_in[1];
    const float* Wq = (const float*)d_in[2];
    const float* bq = (const float*)d_in[3];
    const float* Wk = (const float*)d_in[4];
    const float* bk = (const float*)d_in[5];
    const float* Wv = (const float*)d_in[6];
    const float* bv = (const float*)d_in[7];
    float* out = (float*)d_out;

    cudaFuncSetAttribute(attn_kernel,
                         cudaFuncAttributeMaxDynamicSharedMemorySize, AT_SMEM_BYTES);

    rope_init_kernel<<<(S_*ROT_/2 + 255)/256, 256>>>();

    {   // fp32 -> fp16 planes (H single; W hi/lo)
        dim3 cgrid((unsigned)(((size_t)M_*HID_/4 + 255)/256), 4);
        convert_kernel<<<cgrid, 256>>>(H, Wq, Wk, Wv);
    }

    dim3 ggrid(HID_/BN, M_/BM, 3);        // 32 x 32 x 3
    qkv_kernel<<<ggrid, 256>>>(bq, bk, bv);

    dim3 agrid(S_/AQ, NH_, B_);           // 16 x 16 x 2
    attn_kernel<<<agrid, 256, AT_SMEM_BYTES>>>(am, out);
}

// round 10
// speedup vs baseline: 5.0721x; 1.0921x over previous
#include <cuda_runtime.h>
#include <cuda_fp16.h>
#include <math.h>
#include <stdint.h>

#define B_   2
#define S_   2048
#define HID_ 2048
#define NH_  16
#define HD_  128
#define ROT_ 64
#define M_   (B_*S_)          // 4096 rows in QKV GEMM

// ---------------- scratch (no allocations allowed) ----------------
__device__ __align__(128) __half g_Hh [(size_t)M_*HID_];
__device__ __align__(128) __half g_Whi[3][(size_t)HID_*HID_];
__device__ __align__(128) __half g_Wlo[3][(size_t)HID_*HID_];
__device__ __align__(128) __half g_Qh [(size_t)B_*NH_*S_*HD_];
__device__ __align__(128) __half g_Khi[(size_t)B_*NH_*S_*HD_];
__device__ __align__(128) __half g_Klo[(size_t)B_*NH_*S_*HD_];
__device__ __align__(128) __half g_Vhi[(size_t)B_*NH_*S_*HD_];
__device__ __align__(128) __half g_Vlo[(size_t)B_*NH_*S_*HD_];
__device__ __align__(128) float2 g_rope[S_*ROT_/2];

// ================= helpers =================
__device__ __forceinline__ uint32_t smem_u32(const void* p) {
    return (uint32_t)__cvta_generic_to_shared(p);
}
__device__ __forceinline__ void split_f16(float x, __half& hi, __half& lo) {
    hi = __float2half_rn(x);
    lo = __float2half_rn(x - __half2float(hi));
}
__device__ __forceinline__ uint32_t pack_h2(float x, float y) {
    __half2 t = __floats2half2_rn(x, y);
    return *(uint32_t*)&t;
}
__device__ __forceinline__ void ldmx4(uint32_t& r0, uint32_t& r1, uint32_t& r2, uint32_t& r3, uint32_t a) {
    asm volatile("ldmatrix.sync.aligned.m8n8.x4.shared.b16 {%0,%1,%2,%3},[%4];"
                 : "=r"(r0), "=r"(r1), "=r"(r2), "=r"(r3) : "r"(a));
}
__device__ __forceinline__ void ldmx4t(uint32_t& r0, uint32_t& r1, uint32_t& r2, uint32_t& r3, uint32_t a) {
    asm volatile("ldmatrix.sync.aligned.m8n8.x4.trans.shared.b16 {%0,%1,%2,%3},[%4];"
                 : "=r"(r0), "=r"(r1), "=r"(r2), "=r"(r3) : "r"(a));
}
__device__ __forceinline__ void ldmx2(uint32_t& r0, uint32_t& r1, uint32_t a) {
    asm volatile("ldmatrix.sync.aligned.m8n8.x2.shared.b16 {%0,%1},[%2];"
                 : "=r"(r0), "=r"(r1) : "r"(a));
}
__device__ __forceinline__ void mma_fp16(float* c, const uint32_t* a, const uint32_t* b) {
    asm volatile(
        "mma.sync.aligned.m16n8k16.row.col.f32.f16.f16.f32 "
        "{%0,%1,%2,%3},{%4,%5,%6,%7},{%8,%9},{%0,%1,%2,%3};"
        : "+f"(c[0]), "+f"(c[1]), "+f"(c[2]), "+f"(c[3])
        : "r"(a[0]), "r"(a[1]), "r"(a[2]), "r"(a[3]), "r"(b[0]), "r"(b[1]));
}
__device__ __forceinline__ void cpasync16(uint32_t dst, const void* src) {
    asm volatile("cp.async.cg.shared.global [%0], [%1], 16;" :: "r"(dst), "l"(src));
}
__device__ __forceinline__ void cp_commit() { asm volatile("cp.async.commit_group;" ::: "memory"); }
template<int N> __device__ __forceinline__ void cp_wait() {
    asm volatile("cp.async.wait_group %0;" :: "n"(N) : "memory");
}

// ================= RoPE table init =================
__global__ void rope_init_kernel() {
    int idx = blockIdx.x * 256 + threadIdx.x;
    if (idx < S_*ROT_/2) {
        int s = idx >> 5;
        int i = idx & 31;
        float inv = powf(10000.0f, -(float)(2*i) / (float)ROT_);
        float ang = (float)s * inv;
        float sn, cs; sincosf(ang, &sn, &cs);
        g_rope[idx] = make_float2(sn, cs);
    }
}

// ================= fp32 -> fp16 planes =================
__global__ __launch_bounds__(256)
void convert_kernel(const float* __restrict__ H,
                    const float* __restrict__ Wq,
                    const float* __restrict__ Wk,
                    const float* __restrict__ Wv)
{
    const int t = blockIdx.y;
    const float* src = (t==0) ? H : (t==1) ? Wq : (t==2) ? Wk : Wv;
    const size_t n4 = ((t==0) ? (size_t)M_*HID_ : (size_t)HID_*HID_) / 4;
    size_t i = (size_t)blockIdx.x * 256 + threadIdx.x;
    if (i >= n4) return;
    float4 v = *(const float4*)(src + i*4);
    if (t == 0) {
        uint2 p = make_uint2(pack_h2(v.x, v.y), pack_h2(v.z, v.w));
        *(uint2*)(g_Hh + i*4) = p;
    } else {
        __half h0,l0,h1,l1,h2,l2,h3,l3;
        split_f16(v.x,h0,l0); split_f16(v.y,h1,l1);
        split_f16(v.z,h2,l2); split_f16(v.w,h3,l3);
        uint2 ph = make_uint2(pack_h2(__half2float(h0),__half2float(h1)),
                              pack_h2(__half2float(h2),__half2float(h3)));
        uint2 pl = make_uint2(pack_h2(__half2float(l0),__half2float(l1)),
                              pack_h2(__half2float(l2),__half2float(l3)));
        *(uint2*)(g_Whi[t-1] + i*4) = ph;
        *(uint2*)(g_Wlo[t-1] + i*4) = pl;
    }
}

// ================= QKV projection: fp16x2-split mma GEMM =================
#define BM 128
#define BN 64
#define BK 32
#define NKS (HID_/BK)          // 64
#define QASTR 40               // padded half row stride (80 B)

__global__ __launch_bounds__(256)
void qkv_kernel(const float* __restrict__ bq,
                const float* __restrict__ bk,
                const float* __restrict__ bv)
{
    __shared__ __align__(16) __half sA [2][BM*QASTR];
    __shared__ __align__(16) __half sBh[2][BN*QASTR];
    __shared__ __align__(16) __half sBl[2][BN*QASTR];

    const int z  = blockIdx.z;
    const float* bias = (z==0) ? bq : (z==1) ? bk : bv;
    const __half* Whi_ = g_Whi[z];
    const __half* Wlo_ = g_Wlo[z];

    const int tid  = threadIdx.x;
    const int lane = tid & 31;
    const int wid  = tid >> 5;
    const int wm   = wid & 3;
    const int wn   = wid >> 2;
    const int m0   = blockIdx.y * BM;
    const int n0   = blockIdx.x * BN;

    const uint32_t aB[2]  = { smem_u32(&sA [0][0]), smem_u32(&sA [1][0]) };
    const uint32_t bhB[2] = { smem_u32(&sBh[0][0]), smem_u32(&sBh[1][0]) };
    const uint32_t blB[2] = { smem_u32(&sBl[0][0]), smem_u32(&sBl[1][0]) };

    float acc[2][4][4];
    #pragma unroll
    for (int i=0;i<2;i++)
        #pragma unroll
        for (int j=0;j<4;j++)
            #pragma unroll
            for (int e=0;e<4;e++) acc[i][j][e]=0.f;

    const int a_row = lane & 15;
    const int a_col = ((lane >> 4) & 1) * 8;
    const int b_row = lane & 7;
    const int b_col = ((lane >> 3) & 1) * 8;

    auto load_stage = [&](int st, int k0) {
        #pragma unroll
        for (int it = 0; it < 2; it++) {
            int i = tid + it*256;
            int r = i >> 2, c = i & 3;
            cpasync16(aB[st] + r*80 + c*16, g_Hh + (size_t)(m0 + r)*HID_ + k0 + c*8);
        }
        {
            int r = tid >> 2, c = tid & 3;
            cpasync16(bhB[st] + r*80 + c*16, Whi_ + (size_t)(n0 + r)*HID_ + k0 + c*8);
            cpasync16(blB[st] + r*80 + c*16, Wlo_ + (size_t)(n0 + r)*HID_ + k0 + c*8);
        }
        cp_commit();
    };

    load_stage(0, 0);

    for (int ks = 0; ks < NKS; ks++) {
        const int cur = ks & 1;
        if (ks + 1 < NKS) {
            load_stage(cur ^ 1, (ks+1)*BK);
            cp_wait<1>();
        } else {
            cp_wait<0>();
        }
        __syncthreads();

        #pragma unroll
        for (int k16 = 0; k16 < BK; k16 += 16) {
            uint32_t a[2][4], bh[4][2], bl[4][2];
            #pragma unroll
            for (int mi=0; mi<2; mi++) {
                int row = wm*32 + mi*16 + a_row;
                ldmx4(a[mi][0],a[mi][1],a[mi][2],a[mi][3],
                      aB[cur] + (row*QASTR + k16 + a_col)*2);
            }
            #pragma unroll
            for (int nj=0; nj<4; nj++) {
                int row = wn*32 + nj*8 + b_row;
                ldmx2(bh[nj][0], bh[nj][1], bhB[cur] + (row*QASTR + k16 + b_col)*2);
                ldmx2(bl[nj][0], bl[nj][1], blB[cur] + (row*QASTR + k16 + b_col)*2);
            }
            #pragma unroll
            for (int mi=0; mi<2; mi++)
                #pragma unroll
                for (int nj=0; nj<4; nj++) {
                    mma_fp16(acc[mi][nj], a[mi], bh[nj]);
                    mma_fp16(acc[mi][nj], a[mi], bl[nj]);
                }
        }
        __syncthreads();
    }

    // ---- epilogue: bias + RoPE -> fp16 planes [b][h][s][d] ----
    const float qscale = 0.08838834764831845f;   // fold 1/sqrt(HD) into Q
    #pragma unroll
    for (int mi=0; mi<2; mi++) {
        #pragma unroll
        for (int nj=0; nj<4; nj++) {
            const int n  = n0 + wn*32 + nj*8 + (lane&3)*2;
            const int hh = n >> 7;
            const int d  = n & 127;
            const float bx = __ldg(&bias[n]), by = __ldg(&bias[n+1]);
            #pragma unroll
            for (int hf=0; hf<2; hf++) {
                const int m  = m0 + wm*32 + mi*16 + (lane>>2) + hf*8;
                const int bb = m >> 11;
                const int s  = m & 2047;
                float x = acc[mi][nj][hf*2+0] + bx;
                float y = acc[mi][nj][hf*2+1] + by;
                if (z < 2 && d < ROT_) {
                    float2 sc = g_rope[s*(ROT_/2) + (d>>1)];
                    float nx = x*sc.y - y*sc.x;
                    float ny = y*sc.y + x*sc.x;
                    x = nx; y = ny;
                }
                const size_t o = (((size_t)bb*NH_ + hh)*S_ + s)*(size_t)HD_ + d;
                if (z == 0) {
                    *(uint32_t*)(g_Qh + o) = pack_h2(x*qscale, y*qscale);
                } else {
                    __half xh,xl,yh,yl;
                    split_f16(x, xh, xl);
                    split_f16(y, yh, yl);
                    __half* Phi = (z==1) ? g_Khi : g_Vhi;
                    __half* Plo = (z==1) ? g_Klo : g_Vlo;
                    *(uint32_t*)(Phi + o) = pack_h2(__half2float(xh), __half2float(yh));
                    *(uint32_t*)(Plo + o) = pack_h2(__half2float(xl), __half2float(yl));
                }
            }
        }
    }
}

// ================= causal flash attention (fp16x2, cp.async pipelined) =================
#define AQ  128
#define AK  64
#define KSTR 136     // padded half row stride (272 B)

#define AT_Q    (AQ*KSTR)               // halves
#define AT_P    (AK*KSTR)               // halves per plane
#define AT_STG  (4*AT_P)                // halves per stage (Kh,Kl,Vh,Vl)
// halves offsets
#define OFF_S0  AT_Q
#define OFF_S1  (AT_Q + AT_STG)
#define OFF_MS  (AT_Q + 2*AT_STG)       // then 2*64 floats
#define AT_SMEM_BYTES (OFF_MS*2 + 2*64*4)

__global__ __launch_bounds__(256)
void attn_kernel(const float* __restrict__ amask, float* __restrict__ out)
{
    extern __shared__ __align__(16) char smraw[];
    __half* SM = (__half*)smraw;
    __half* Qs = SM;
    float*  msbase = (float*)(SM + OFF_MS);

    const int qt = (gridDim.x - 1) - blockIdx.x;   // heavy tiles first
    const int h  = blockIdx.y, b = blockIdx.z;
    const size_t hoff = ((size_t)b*NH_ + h)*S_*HD_;
    const __half* Qg  = g_Qh  + hoff;
    const __half* Khg = g_Khi + hoff;
    const __half* Klg = g_Klo + hoff;
    const __half* Vhg = g_Vhi + hoff;
    const __half* Vlg = g_Vlo + hoff;

    const int tid  = threadIdx.x;
    const int lane = tid & 31;
    const int w    = tid >> 5;
    const int qbase = qt*AQ + w*16;

    const uint32_t smb = smem_u32(SM);

    // ---- stage prefetch (cp.async): K/V planes + amask slice ----
    auto load_kv = [&](int kt, int st) {
        const uint32_t sb = smb + (st ? OFF_S1 : OFF_S0)*2;
        #pragma unroll
        for (int it = 0; it < 4; it++) {
            int idx = tid + it*256;            // 1024 chunks of 16B per plane
            int r = idx >> 4;
            int c = (idx & 15) * 8;            // halves
            const size_t so = (size_t)(kt*AK + r)*HD_ + c;
            const uint32_t d = sb + (r*KSTR + c)*2;
            cpasync16(d,            Khg + so);
            cpasync16(d + AT_P*2,   Klg + so);
            cpasync16(d + AT_P*4,   Vhg + so);
            cpasync16(d + AT_P*6,   Vlg + so);
        }
        if (tid < 16)
            cpasync16(smb + OFF_MS*2 + st*256 + tid*16,
                      amask + (size_t)b*S_ + kt*AK + tid*4);
    };

    // ---- prologue: Q + stage 0 in one group ----
    #pragma unroll
    for (int it = 0; it < 8; it++) {
        int idx = tid + it*256;                // 2048 chunks of 16B
        int r = idx >> 4;
        int c = (idx & 15) * 8;
        cpasync16(smb + (r*KSTR + c)*2, Qg + (size_t)(qt*AQ + r)*HD_ + c);
    }
    load_kv(0, 0);
    cp_commit();

    float o[16][4];
    #pragma unroll
    for (int nt=0; nt<16; nt++)
        #pragma unroll
        for (int e=0;e<4;e++) o[nt][e]=0.f;

    float m0 = -INFINITY, m1 = -INFINITY, l0 = 0.f, l1 = 0.f;

    const int qa_row = lane & 15;
    const int qa_col = (lane >> 4) * 8;
    const int kb_key = (lane & 7) + ((lane >> 4) << 3);
    const int kb_col = ((lane >> 3) & 1) * 8;
    const int vb_key = (lane & 7) + (((lane >> 3) & 1) << 3);
    const int vb_col = (lane >> 4) * 8;

    // wait prologue, hoist Q fragments (kt-invariant)
    cp_wait<0>();
    __syncthreads();
    uint32_t qf[8][4];
    #pragma unroll
    for (int ks = 0; ks < 8; ks++)
        ldmx4(qf[ks][0],qf[ks][1],qf[ks][2],qf[ks][3],
              smb + ((w*16+qa_row)*KSTR + ks*16 + qa_col)*2);

    const int ktmax = 2*qt + 1;
    for (int kt = 0; kt <= ktmax; kt++) {
        const int cur = kt & 1;
        if (kt > 0) { cp_wait<0>(); __syncthreads(); }
        // prefetch next tile into the buffer freed by iteration kt-1
        if (kt + 1 <= ktmax) { load_kv(kt+1, cur ^ 1); cp_commit(); }

        const uint32_t ksb = smb + (cur ? OFF_S1 : OFF_S0)*2;
        const float* ms = msbase + cur*64;

        // ---- S = Q K^T (Q single pre-scaled, K hi+lo) ----
        float s[8][4];
        #pragma unroll
        for (int nt=0; nt<8; nt++)
            #pragma unroll
            for (int e=0;e<4;e++) s[nt][e]=0.f;

        #pragma unroll
        for (int ks = 0; ks < 8; ks++) {
            const int d0 = ks*16;
            #pragma unroll
            for (int ntp = 0; ntp < 4; ntp++) {
                const int n0 = ntp*16;
                uint32_t bh[4], bl[4];
                ldmx4(bh[0],bh[1],bh[2],bh[3], ksb + ((n0+kb_key)*KSTR + d0 + kb_col)*2);
                ldmx4(bl[0],bl[1],bl[2],bl[3], ksb + AT_P*2 + ((n0+kb_key)*KSTR + d0 + kb_col)*2);
                mma_fp16(s[ntp*2],   qf[ks], &bh[0]);
                mma_fp16(s[ntp*2],   qf[ks], &bl[0]);
                mma_fp16(s[ntp*2+1], qf[ks], &bh[2]);
                mma_fp16(s[ntp*2+1], qf[ks], &bl[2]);
            }
        }

        // ---- causal + amask (scale already folded into Q) ----
        const int qi0 = qbase + (lane>>2);
        const int qi1 = qi0 + 8;
        #pragma unroll
        for (int nt=0; nt<8; nt++) {
            const int kc = kt*AK + nt*8 + (lane&3)*2;
            const float am0 = ms[nt*8 + (lane&3)*2];
            const float am1 = ms[nt*8 + (lane&3)*2 + 1];
            s[nt][0] = ((kc   <= qi0) ? s[nt][0] : -10000.f) + am0;
            s[nt][1] = ((kc+1 <= qi0) ? s[nt][1] : -10000.f) + am1;
            s[nt][2] = ((kc   <= qi1) ? s[nt][2] : -10000.f) + am0;
            s[nt][3] = ((kc+1 <= qi1) ? s[nt][3] : -10000.f) + am1;
        }

        // ---- online softmax ----
        float mx0 = -INFINITY, mx1 = -INFINITY;
        #pragma unroll
        for (int nt=0; nt<8; nt++) {
            mx0 = fmaxf(mx0, fmaxf(s[nt][0], s[nt][1]));
            mx1 = fmaxf(mx1, fmaxf(s[nt][2], s[nt][3]));
        }
        mx0 = fmaxf(mx0, __shfl_xor_sync(0xffffffffu, mx0, 1));
        mx0 = fmaxf(mx0, __shfl_xor_sync(0xffffffffu, mx0, 2));
        mx1 = fmaxf(mx1, __shfl_xor_sync(0xffffffffu, mx1, 1));
        mx1 = fmaxf(mx1, __shfl_xor_sync(0xffffffffu, mx1, 2));
        const float mn0 = fmaxf(m0, mx0), mn1 = fmaxf(m1, mx1);
        const float al0 = __expf(m0 - mn0), al1 = __expf(m1 - mn1);
        m0 = mn0; m1 = mn1;

        float sum0 = 0.f, sum1 = 0.f;
        #pragma unroll
        for (int nt=0; nt<8; nt++) {
            s[nt][0] = __expf(s[nt][0] - mn0);
            s[nt][1] = __expf(s[nt][1] - mn0);
            s[nt][2] = __expf(s[nt][2] - mn1);
            s[nt][3] = __expf(s[nt][3] - mn1);
            sum0 += s[nt][0] + s[nt][1];
            sum1 += s[nt][2] + s[nt][3];
        }
        sum0 += __shfl_xor_sync(0xffffffffu, sum0, 1);
        sum0 += __shfl_xor_sync(0xffffffffu, sum0, 2);
        sum1 += __shfl_xor_sync(0xffffffffu, sum1, 1);
        sum1 += __shfl_xor_sync(0xffffffffu, sum1, 2);
        l0 = l0*al0 + sum0;
        l1 = l1*al1 + sum1;

        #pragma unroll
        for (int nt=0; nt<16; nt++) {
            o[nt][0] *= al0; o[nt][1] *= al0;
            o[nt][2] *= al1; o[nt][3] *= al1;
        }

        // ---- O += P V (P single fp16, V hi+lo) ----
        #pragma unroll
        for (int ks = 0; ks < 4; ks++) {
            const int t0 = 2*ks, t1 = 2*ks+1;
            uint32_t pa[4];
            pa[0] = pack_h2(s[t0][0], s[t0][1]);
            pa[1] = pack_h2(s[t0][2], s[t0][3]);
            pa[2] = pack_h2(s[t1][0], s[t1][1]);
            pa[3] = pack_h2(s[t1][2], s[t1][3]);
            const int k0 = ks*16;
            #pragma unroll
            for (int ntp = 0; ntp < 8; ntp++) {
                const int n0 = ntp*16;
                uint32_t vh[4], vl[4];
                ldmx4t(vh[0],vh[1],vh[2],vh[3], ksb + AT_P*4 + ((k0+vb_key)*KSTR + n0 + vb_col)*2);
                ldmx4t(vl[0],vl[1],vl[2],vl[3], ksb + AT_P*6 + ((k0+vb_key)*KSTR + n0 + vb_col)*2);
                mma_fp16(o[ntp*2],   pa, &vh[0]);
                mma_fp16(o[ntp*2],   pa, &vl[0]);
                mma_fp16(o[ntp*2+1], pa, &vh[2]);
                mma_fp16(o[ntp*2+1], pa, &vl[2]);
            }
        }
    }

    // ---- normalize + write out[b][s][h*HD+d] ----
    const float inv0 = 1.0f / l0;
    const float inv1 = 1.0f / l1;
    const int r0 = qbase + (lane>>2);
    const int r1 = r0 + 8;
    #pragma unroll
    for (int nt=0; nt<16; nt++) {
        const int col = h*HD_ + nt*8 + (lane&3)*2;
        float2 w0 = make_float2(o[nt][0]*inv0, o[nt][1]*inv0);
        float2 w1 = make_float2(o[nt][2]*inv1, o[nt][3]*inv1);
        *(float2*)&out[(size_t)(b*S_ + r0)*HID_ + col] = w0;
        *(float2*)&out[(size_t)(b*S_ + r1)*HID_ + col] = w1;
    }
}

// ================= launch =================
extern "C" void kernel_launch(void* const* d_in, const int* in_sizes, int n_in,
                              void* d_out, int out_size)
{
    const float* H  = (const float*)d_in[0];
    const float* am = (const float*)d_in[1];
    const float* Wq = (const float*)d_in[2];
    const float* bq = (const float*)d_in[3];
    const float* Wk = (const float*)d_in[4];
    const float* bk = (const float*)d_in[5];
    const float* Wv = (const float*)d_in[6];
    const float* bv = (const float*)d_in[7];
    float* out = (float*)d_out;

    cudaFuncSetAttribute(attn_kernel,
                         cudaFuncAttributeMaxDynamicSharedMemorySize, AT_SMEM_BYTES);

    rope_init_kernel<<<(S_*ROT_/2 + 255)/256, 256>>>();

    {   // fp32 -> fp16 planes (H single; W hi/lo)
        dim3 cgrid((unsigned)(((size_t)M_*HID_/4 + 255)/256), 4);
        convert_kernel<<<cgrid, 256>>>(H, Wq, Wk, Wv);
    }

    dim3 ggrid(HID_/BN, M_/BM, 3);        // 32 x 32 x 3
    qkv_kernel<<<ggrid, 256>>>(bq, bk, bv);

    dim3 agrid(S_/AQ, NH_, B_);           // 16 x 16 x 2
    attn_kernel<<<agrid, 256, AT_SMEM_BYTES>>>(am, out);
}